// round 15
// baseline (speedup 1.0000x reference)
#include <cuda_runtime.h>
#include <cuda_fp16.h>
#include <cstdint>

#define N_NODES 100000
#define N_EDGES 3200000
#define D_IN 83
#define XP 96          // x/ax row stride in halves (192B)
#define D_HID 1024
#define NC 25
#define ZP 32          // z row stride in halves (64B)
#define NBLK 391
#define CONV_Y 4       // nodes per conv block

// ---------------- scratch ----------------
__device__ __half g_xh[(size_t)N_NODES * XP];
__device__ __half g_axh[(size_t)N_NODES * XP];
__device__ __half g_zh[(size_t)N_NODES * ZP];
__device__ int    g_cnt[N_NODES];
__device__ int    g_rowptr[N_NODES + 1];
__device__ int    g_cur[N_NODES + 1];
__device__ int    g_bsum[NBLK];
__device__ int    g_boff[NBLK];
__device__ int2   g_edge[N_EDGES];

__device__ __forceinline__ uint32_t smem_u32(const void* p) {
    uint32_t a;
    asm("{ .reg .u64 t; cvta.to.shared.u64 t, %1; cvt.u32.u64 %0, t; }" : "=r"(a) : "l"(p));
    return a;
}

// ---------------- 1. conv prelude: 4 nodes/block (also zeroes g_cnt) -------
__global__ void conv_relu_kernel(const float* __restrict__ feat,
                                 const float* __restrict__ conv_w,
                                 const float* __restrict__ conv_b) {
    __shared__ float srow[CONV_Y][D_IN];
    __shared__ float sw[5];
    __shared__ float sb;
    int tx = threadIdx.x;             // 0..95
    int ty = threadIdx.y;             // 0..CONV_Y-1
    int n = blockIdx.x * CONV_Y + ty;
    if (ty == 0) {
        if (tx < 5) sw[tx] = conv_w[tx] + conv_w[5 + tx] + conv_w[10 + tx] + conv_w[15 + tx];
        if (tx == 5) sb = conv_b[0] + conv_b[1] + conv_b[2] + conv_b[3];
    }
    if (tx == 90) g_cnt[n] = 0;
    if (tx < D_IN) srow[ty][tx] = feat[(size_t)n * D_IN + tx];
    __syncthreads();
    float r = 0.f;
    if (tx < D_IN) {
        float s = sb;
        #pragma unroll
        for (int k = 0; k < 5; k++) {
            int j = tx + k - 2;
            if (j >= 0 && j < D_IN) s += srow[ty][j] * sw[k];
        }
        r = fmaxf(s, 0.f);
    }
    g_xh[(size_t)n * XP + tx] = __float2half_rn(r);
}

// ---------------- CSR build (atomic-cursor scatter) ------------------------
__global__ void count_kernel(const int* __restrict__ row) {
    int e = blockIdx.x * blockDim.x + threadIdx.x;
    if (e < N_EDGES) atomicAdd(&g_cnt[row[e]], 1);
}
__global__ void scan1_kernel() {
    __shared__ int s[256];
    int t = threadIdx.x;
    int i = blockIdx.x * 256 + t;
    int v = (i < N_NODES) ? g_cnt[i] : 0;
    s[t] = v;
    __syncthreads();
    #pragma unroll
    for (int d = 1; d < 256; d <<= 1) {
        int x = (t >= d) ? s[t - d] : 0;
        __syncthreads();
        s[t] += x;
        __syncthreads();
    }
    if (i < N_NODES) g_rowptr[i + 1] = s[t];
    if (t == 255) g_bsum[blockIdx.x] = s[255];
}
__global__ void scan2_kernel() {
    __shared__ int s[512];
    int t = threadIdx.x;
    s[t] = (t < NBLK) ? g_bsum[t] : 0;
    __syncthreads();
    #pragma unroll
    for (int d = 1; d < 512; d <<= 1) {
        int x = (t >= d) ? s[t - d] : 0;
        __syncthreads();
        s[t] += x;
        __syncthreads();
    }
    if (t < NBLK) g_boff[t] = (t > 0) ? s[t - 1] : 0;
}
__global__ void scan3_kernel() {
    int t = threadIdx.x;
    int i = blockIdx.x * 256 + t;
    if (i < N_NODES) {
        int val = g_rowptr[i + 1] + g_boff[blockIdx.x];
        g_rowptr[i + 1] = val;
        g_cur[i + 1] = val;
    }
    if (i == 0) { g_rowptr[0] = 0; g_cur[0] = 0; }
}
__global__ void scatter_kernel(const float* __restrict__ val,
                               const int* __restrict__ row,
                               const int* __restrict__ col) {
    int e = blockIdx.x * blockDim.x + threadIdx.x;
    if (e < N_EDGES) {
        int r = row[e];
        int pos = atomicAdd(&g_cur[r], 1);
        g_edge[pos] = make_int2(col[e], __float_as_int(val[e]));
    }
}

// ---------------- 3. SpMM1 (gather, 2-edge unroll + edge prefetch) ---------
__global__ void spmm_x_csr_kernel() {
    int w = (blockIdx.x * blockDim.x + threadIdx.x) >> 5;
    int lane = threadIdx.x & 31;
    if (w >= N_NODES) return;
    int s = g_rowptr[w], e = g_rowptr[w + 1];
    float2 a0 = make_float2(0.f, 0.f), a1 = make_float2(0.f, 0.f);
    float2 b0 = make_float2(0.f, 0.f), b1 = make_float2(0.f, 0.f);
    bool lo = lane < 16;
    int j = s;

    auto process2 = [&](int2 e0, int2 e1) {
        float v0 = __int_as_float(e0.y), v1 = __int_as_float(e1.y);
        const __half2* s0 = (const __half2*)(g_xh + (size_t)e0.x * XP);
        const __half2* s1 = (const __half2*)(g_xh + (size_t)e1.x * XP);
        float2 f0 = __half22float2(s0[lane]);
        float2 f1 = __half22float2(s1[lane]);
        a0.x = fmaf(v0, f0.x, a0.x); a0.y = fmaf(v0, f0.y, a0.y);
        b0.x = fmaf(v1, f1.x, b0.x); b0.y = fmaf(v1, f1.y, b0.y);
        if (lo) {
            float2 g0 = __half22float2(s0[32 + lane]);
            float2 g1 = __half22float2(s1[32 + lane]);
            a1.x = fmaf(v0, g0.x, a1.x); a1.y = fmaf(v0, g0.y, a1.y);
            b1.x = fmaf(v1, g1.x, b1.x); b1.y = fmaf(v1, g1.y, b1.y);
        }
    };

    if (e - s >= 2) {
        int2 e0 = g_edge[s], e1 = g_edge[s + 1];
        for (; j + 3 < e; j += 2) {
            int2 n0 = g_edge[j + 2], n1 = g_edge[j + 3];   // prefetch next pair
            process2(e0, e1);
            e0 = n0; e1 = n1;
        }
        process2(e0, e1);
        j += 2;
    }
    if (j < e) {
        int2 e0 = g_edge[j];
        float v0 = __int_as_float(e0.y);
        const __half2* s0 = (const __half2*)(g_xh + (size_t)e0.x * XP);
        float2 f0 = __half22float2(s0[lane]);
        a0.x = fmaf(v0, f0.x, a0.x); a0.y = fmaf(v0, f0.y, a0.y);
        if (lo) {
            float2 g0 = __half22float2(s0[32 + lane]);
            a1.x = fmaf(v0, g0.x, a1.x); a1.y = fmaf(v0, g0.y, a1.y);
        }
    }
    __half2* dst = (__half2*)(g_axh + (size_t)w * XP);
    dst[lane] = __floats2half2_rn(a0.x + b0.x, a0.y + b0.y);
    if (lo)
        dst[32 + lane] = __floats2half2_rn(a1.x + b1.x, a1.y + b1.y);
}

// ---------------- 4+5 fused fp16 ldmatrix: z = relu(ax@W1+b1)@W2 -----------
#define AST  104
#define B1ST 136
#define HST  136
#define W2ST 40
#define OFF_AS  0
#define OFF_B1  (128 * AST * 2)
#define OFF_HS  (OFF_B1 + 96 * B1ST * 2)
#define OFF_W2  (OFF_HS + 128 * HST * 2)
#define OFF_SB1 (OFF_W2 + 128 * W2ST * 2)
#define FUSED_SMEM (OFF_SB1 + D_HID * 4)

__device__ __forceinline__ void ldsm_x4(uint32_t* r, uint32_t addr) {
    asm volatile("ldmatrix.sync.aligned.m8n8.x4.shared.b16 {%0,%1,%2,%3}, [%4];"
        : "=r"(r[0]), "=r"(r[1]), "=r"(r[2]), "=r"(r[3]) : "r"(addr));
}
__device__ __forceinline__ void ldsm_x4_t(uint32_t* r, uint32_t addr) {
    asm volatile("ldmatrix.sync.aligned.m8n8.x4.trans.shared.b16 {%0,%1,%2,%3}, [%4];"
        : "=r"(r[0]), "=r"(r[1]), "=r"(r[2]), "=r"(r[3]) : "r"(addr));
}
__device__ __forceinline__ void mma_f16(float* d, const uint32_t* a, const uint32_t* b) {
    asm volatile(
        "mma.sync.aligned.m16n8k16.row.col.f32.f16.f16.f32 "
        "{%0,%1,%2,%3}, {%4,%5,%6,%7}, {%8,%9}, {%0,%1,%2,%3};"
        : "+f"(d[0]), "+f"(d[1]), "+f"(d[2]), "+f"(d[3])
        : "r"(a[0]), "r"(a[1]), "r"(a[2]), "r"(a[3]), "r"(b[0]), "r"(b[1]));
}

__global__ __launch_bounds__(256, 2) void fused_gemm_kernel(const float* __restrict__ W1,
                                                            const float* __restrict__ b1,
                                                            const float* __restrict__ W2) {
    extern __shared__ __align__(16) char smem_raw[];
    __half* As  = (__half*)(smem_raw + OFF_AS);
    __half* B1s = (__half*)(smem_raw + OFF_B1);
    __half* Hs  = (__half*)(smem_raw + OFF_HS);
    __half* W2s = (__half*)(smem_raw + OFF_W2);
    float*  sB1 = (float*)(smem_raw + OFF_SB1);
    uint32_t sbase = smem_u32(smem_raw);

    int t = threadIdx.x;
    int wid = t >> 5, lane = t & 31;
    int g = lane >> 2, tg = lane & 3;
    int l15 = lane & 15;
    int off8 = (lane >> 4) << 3;
    int m0 = blockIdx.x * 128;

    #pragma unroll
    for (int it = 0; it < 6; it++) {
        int flat = it * 256 + t;
        int rr = flat / 12, q = flat % 12;
        uint4 v = make_uint4(0u, 0u, 0u, 0u);
        int gr = m0 + rr;
        if (gr < N_NODES) v = *(const uint4*)&g_axh[(size_t)gr * XP + q * 8];
        *(uint4*)(As + rr * AST + q * 8) = v;
    }
    for (int i = t; i < D_HID; i += 256) sB1[i] = b1[i];

    int wm = (wid & 1) * 64;
    int wn = (wid >> 1) * 32;

    float accz[4][4];
    #pragma unroll
    for (int ct = 0; ct < 4; ct++)
        #pragma unroll
        for (int i = 0; i < 4; i++) accz[ct][i] = 0.f;

    for (int nt = 0; nt < 8; nt++) {
        int n0 = nt * 128;
        #pragma unroll
        for (int it = 0; it < 12; it++) {
            int flat = it * 256 + t;
            int k = flat >> 5, n4 = flat & 31;
            float4 v = make_float4(0.f, 0.f, 0.f, 0.f);
            if (k < D_IN) v = *(const float4*)&W1[(size_t)k * D_HID + n0 + n4 * 4];
            __half2* dst = (__half2*)(B1s + k * B1ST + n4 * 4);
            dst[0] = __floats2half2_rn(v.x, v.y);
            dst[1] = __floats2half2_rn(v.z, v.w);
        }
        #pragma unroll
        for (int it = 0; it < 8; it++) {
            int idx = it * 256 + t;
            int kk = idx >> 4, c2 = idx & 15;
            int c = c2 * 2;
            float w0 = (c < NC) ? W2[(size_t)(n0 + kk) * NC + c] : 0.f;
            float w1 = (c + 1 < NC) ? W2[(size_t)(n0 + kk) * NC + c + 1] : 0.f;
            *(__half2*)(W2s + kk * W2ST + c) = __floats2half2_rn(w0, w1);
        }
        __syncthreads();

        #pragma unroll
        for (int n2h = 0; n2h < 2; n2h++) {
            float acc1[4][2][4];
            #pragma unroll
            for (int mt = 0; mt < 4; mt++)
                #pragma unroll
                for (int n2 = 0; n2 < 2; n2++)
                    #pragma unroll
                    for (int i = 0; i < 4; i++) acc1[mt][n2][i] = 0.f;

            #pragma unroll
            for (int ks = 0; ks < 6; ks++) {
                int k0 = ks * 16;
                uint32_t a[4][4];
                #pragma unroll
                for (int mt = 0; mt < 4; mt++)
                    ldsm_x4(a[mt], sbase + OFF_AS +
                            ((wm + mt * 16 + l15) * AST + k0 + off8) * 2);
                uint32_t bf[4];
                ldsm_x4_t(bf, sbase + OFF_B1 +
                          ((k0 + l15) * B1ST + wn + n2h * 16 + off8) * 2);
                #pragma unroll
                for (int mt = 0; mt < 4; mt++) {
                    mma_f16(acc1[mt][0], a[mt], bf + 0);
                    mma_f16(acc1[mt][1], a[mt], bf + 2);
                }
            }
            #pragma unroll
            for (int n2 = 0; n2 < 2; n2++) {
                int col = wn + n2h * 16 + n2 * 8 + tg * 2;
                float bz0 = sB1[n0 + col], bz1 = sB1[n0 + col + 1];
                #pragma unroll
                for (int mt = 0; mt < 4; mt++) {
                    int r0 = wm + mt * 16 + g;
                    *(__half2*)(Hs + r0 * HST + col) =
                        __floats2half2_rn(fmaxf(acc1[mt][n2][0] + bz0, 0.f),
                                          fmaxf(acc1[mt][n2][1] + bz1, 0.f));
                    *(__half2*)(Hs + (r0 + 8) * HST + col) =
                        __floats2half2_rn(fmaxf(acc1[mt][n2][2] + bz0, 0.f),
                                          fmaxf(acc1[mt][n2][3] + bz1, 0.f));
                }
            }
        }
        __syncthreads();

        #pragma unroll
        for (int ks = 0; ks < 8; ks++) {
            int k0 = ks * 16;
            uint32_t ah[4];
            ldsm_x4(ah, sbase + OFF_HS + ((wid * 16 + l15) * HST + k0 + off8) * 2);
            uint32_t bw[8];
            ldsm_x4_t(bw + 0, sbase + OFF_W2 + ((k0 + l15) * W2ST + 0 + off8) * 2);
            ldsm_x4_t(bw + 4, sbase + OFF_W2 + ((k0 + l15) * W2ST + 16 + off8) * 2);
            mma_f16(accz[0], ah, bw + 0);
            mma_f16(accz[1], ah, bw + 2);
            mma_f16(accz[2], ah, bw + 4);
            mma_f16(accz[3], ah, bw + 6);
        }
        __syncthreads();
    }

    #pragma unroll
    for (int ct = 0; ct < 4; ct++) {
        int col = ct * 8 + tg * 2;
        int r0 = m0 + wid * 16 + g;
        if (r0 < N_NODES)
            *(__half2*)&g_zh[(size_t)r0 * ZP + col] =
                __floats2half2_rn(accz[ct][0], accz[ct][1]);
        int r1 = r0 + 8;
        if (r1 < N_NODES)
            *(__half2*)&g_zh[(size_t)r1 * ZP + col] =
                __floats2half2_rn(accz[ct][2], accz[ct][3]);
    }
}

// ---------------- 7. SpMM2: dual-half warp, same row, shfl combine ---------
__global__ void spmm_z_csr_kernel(const float* __restrict__ b2,
                                  float* __restrict__ out) {
    int w = (blockIdx.x * blockDim.x + threadIdx.x) >> 5;
    int lane = threadIdx.x & 31;
    if (w >= N_NODES) return;
    int s = g_rowptr[w], e = g_rowptr[w + 1];
    int hi = lane >> 4;
    int c = lane & 15;
    bool act = c < 13;
    float2 acc = make_float2(0.f, 0.f);
    int j = s;
    for (; j + 1 < e; j += 2) {
        int2 ee = g_edge[j + hi];
        float v = __int_as_float(ee.y);
        if (act) {
            float2 f = __half22float2(((const __half2*)(g_zh + (size_t)ee.x * ZP))[c]);
            acc.x = fmaf(v, f.x, acc.x);
            acc.y = fmaf(v, f.y, acc.y);
        }
    }
    if (j < e && hi == 0) {
        int2 ee = g_edge[j];
        float v = __int_as_float(ee.y);
        if (act) {
            float2 f = __half22float2(((const __half2*)(g_zh + (size_t)ee.x * ZP))[c]);
            acc.x = fmaf(v, f.x, acc.x);
            acc.y = fmaf(v, f.y, acc.y);
        }
    }
    acc.x += __shfl_down_sync(0xffffffffu, acc.x, 16);
    acc.y += __shfl_down_sync(0xffffffffu, acc.y, 16);
    if (lane < 13) {
        int c0 = lane * 2;
        out[(size_t)w * NC + c0] = acc.x + b2[c0];
        if (c0 + 1 < NC)
            out[(size_t)w * NC + c0 + 1] = acc.y + b2[c0 + 1];
    }
}

// ---------------- launch ----------------
extern "C" void kernel_launch(void* const* d_in, const int* in_sizes, int n_in,
                              void* d_out, int out_size) {
    const float* feature = (const float*)d_in[0];
    const float* conv_w  = (const float*)d_in[1];
    const float* conv_b  = (const float*)d_in[2];
    const float* W1      = (const float*)d_in[3];
    const float* b1      = (const float*)d_in[4];
    const float* W2      = (const float*)d_in[5];
    const float* b2      = (const float*)d_in[6];
    const float* adj_val = (const float*)d_in[7];
    const int*   e_row   = (const int*)d_in[8];
    const int*   e_col   = (const int*)d_in[9];
    float* out = (float*)d_out;

    cudaFuncSetAttribute(fused_gemm_kernel, cudaFuncAttributeMaxDynamicSharedMemorySize, FUSED_SMEM);

    const int EB = (N_EDGES + 255) / 256;
    const int WB = (N_NODES * 32 + 255) / 256;

    {
        dim3 blk(96, CONV_Y);
        conv_relu_kernel<<<N_NODES / CONV_Y, blk>>>(feature, conv_w, conv_b);
    }
    count_kernel<<<EB, 256>>>(e_row);
    scan1_kernel<<<NBLK, 256>>>();
    scan2_kernel<<<1, 512>>>();
    scan3_kernel<<<NBLK, 256>>>();
    scatter_kernel<<<EB, 256>>>(adj_val, e_row, e_col);
    spmm_x_csr_kernel<<<WB, 256>>>();
    fused_gemm_kernel<<<(N_NODES + 127) / 128, 256, FUSED_SMEM>>>(W1, b1, W2);
    spmm_z_csr_kernel<<<WB, 256>>>(b2, out);
}

// round 16
// speedup vs baseline: 1.1391x; 1.1391x over previous
#include <cuda_runtime.h>
#include <cuda_fp16.h>
#include <cstdint>

#define N_NODES 100000
#define N_EDGES 3200000
#define D_IN 83
#define XP 96          // x/ax row stride in halves (192B)
#define D_HID 1024
#define NC 25
#define ZP 32          // z row stride in halves (64B)
#define NBLK2 196      // ceil(N_NODES/512)
#define CONV_Y 4       // nodes per conv block

// ---------------- scratch ----------------
__device__ __half g_xh[(size_t)N_NODES * XP];
__device__ __half g_axh[(size_t)N_NODES * XP];
__device__ __half g_zh[(size_t)N_NODES * ZP];
__device__ __half g_w1h[96 * D_HID];      // W1 fp16, k-padded to 96
__device__ __half g_w2h[D_HID * 32];      // W2 fp16, c-padded to 32
__device__ int    g_cnt[N_NODES];
__device__ int    g_rowptr[N_NODES + 1];
__device__ int    g_cur[N_NODES + 1];
__device__ int    g_bsum[NBLK2];
__device__ int2   g_edge[N_EDGES];

__device__ __forceinline__ uint32_t smem_u32(const void* p) {
    uint32_t a;
    asm("{ .reg .u64 t; cvta.to.shared.u64 t, %1; cvt.u32.u64 %0, t; }" : "=r"(a) : "l"(p));
    return a;
}

// ---------------- 0. weight pre-convert (fp32 -> fp16, zero-padded) --------
__global__ void prep_w_kernel(const float* __restrict__ W1,
                              const float* __restrict__ W2) {
    int i = blockIdx.x * blockDim.x + threadIdx.x;
    if (i < 96 * 512) {                       // W1h: 96*1024 halves = 49152 half2
        int k = i >> 9, n2 = i & 511;
        float2 v = make_float2(0.f, 0.f);
        if (k < D_IN) v = *(const float2*)&W1[(size_t)k * D_HID + n2 * 2];
        ((__half2*)g_w1h)[i] = __floats2half2_rn(v.x, v.y);
    }
    int j = i - 96 * 512;
    if (j >= 0 && j < D_HID * 16) {           // W2h: 1024*32 halves = 16384 half2
        int kk = j >> 4, c = (j & 15) * 2;
        float w0 = (c < NC) ? W2[(size_t)kk * NC + c] : 0.f;
        float w1 = (c + 1 < NC) ? W2[(size_t)kk * NC + c + 1] : 0.f;
        ((__half2*)g_w2h)[j] = __floats2half2_rn(w0, w1);
    }
}

// ---------------- 1. conv prelude: 4 nodes/block (also zeroes g_cnt) -------
__global__ void conv_relu_kernel(const float* __restrict__ feat,
                                 const float* __restrict__ conv_w,
                                 const float* __restrict__ conv_b) {
    __shared__ float srow[CONV_Y][D_IN];
    __shared__ float sw[5];
    __shared__ float sb;
    int tx = threadIdx.x;
    int ty = threadIdx.y;
    int n = blockIdx.x * CONV_Y + ty;
    if (ty == 0) {
        if (tx < 5) sw[tx] = conv_w[tx] + conv_w[5 + tx] + conv_w[10 + tx] + conv_w[15 + tx];
        if (tx == 5) sb = conv_b[0] + conv_b[1] + conv_b[2] + conv_b[3];
    }
    if (tx == 90) g_cnt[n] = 0;
    if (tx < D_IN) srow[ty][tx] = feat[(size_t)n * D_IN + tx];
    __syncthreads();
    float r = 0.f;
    if (tx < D_IN) {
        float s = sb;
        #pragma unroll
        for (int k = 0; k < 5; k++) {
            int j = tx + k - 2;
            if (j >= 0 && j < D_IN) s += srow[ty][j] * sw[k];
        }
        r = fmaxf(s, 0.f);
    }
    g_xh[(size_t)n * XP + tx] = __float2half_rn(r);
}

// ---------------- CSR build ----------------
__global__ void count_kernel(const int* __restrict__ row) {
    int e = blockIdx.x * blockDim.x + threadIdx.x;
    if (e < N_EDGES) atomicAdd(&g_cnt[row[e]], 1);
}
__global__ void scan1_kernel() {
    __shared__ int s[512];
    int t = threadIdx.x;
    int i = blockIdx.x * 512 + t;
    int v = (i < N_NODES) ? g_cnt[i] : 0;
    s[t] = v;
    __syncthreads();
    #pragma unroll
    for (int d = 1; d < 512; d <<= 1) {
        int x = (t >= d) ? s[t - d] : 0;
        __syncthreads();
        s[t] += x;
        __syncthreads();
    }
    if (i < N_NODES) g_rowptr[i + 1] = s[t];
    if (t == 511) g_bsum[blockIdx.x] = s[511];
}
// scan2+scan3 merged: every block redundantly scans the 196 block sums.
__global__ void scan23_kernel() {
    __shared__ int sb[512];
    int t = threadIdx.x;
    sb[t] = (t < NBLK2) ? g_bsum[t] : 0;
    __syncthreads();
    #pragma unroll
    for (int d = 1; d < 512; d <<= 1) {
        int x = (t >= d) ? sb[t - d] : 0;
        __syncthreads();
        sb[t] += x;
        __syncthreads();
    }
    int b = blockIdx.x;
    int offv = (b > 0) ? sb[b - 1] : 0;
    int i = b * 512 + t;
    if (i < N_NODES) {
        int val = g_rowptr[i + 1] + offv;
        g_rowptr[i + 1] = val;
        g_cur[i + 1] = val;
    }
    if (i == 0) { g_rowptr[0] = 0; g_cur[0] = 0; }
}
__global__ void scatter_kernel(const float* __restrict__ val,
                               const int* __restrict__ row,
                               const int* __restrict__ col) {
    int e = blockIdx.x * blockDim.x + threadIdx.x;
    if (e < N_EDGES) {
        int r = row[e];
        int pos = atomicAdd(&g_cur[r], 1);
        g_edge[pos] = make_int2(col[e], __float_as_int(val[e]));
    }
}

// ---------------- 3. SpMM1 (gather, R14-proven 2-edge unroll) --------------
__global__ void spmm_x_csr_kernel() {
    int w = (blockIdx.x * blockDim.x + threadIdx.x) >> 5;
    int lane = threadIdx.x & 31;
    if (w >= N_NODES) return;
    int s = g_rowptr[w], e = g_rowptr[w + 1];
    float2 a0 = make_float2(0.f, 0.f), a1 = make_float2(0.f, 0.f);
    float2 b0 = make_float2(0.f, 0.f), b1 = make_float2(0.f, 0.f);
    int j = s;
    for (; j + 1 < e; j += 2) {
        int2 e0 = g_edge[j], e1 = g_edge[j + 1];
        float v0 = __int_as_float(e0.y), v1 = __int_as_float(e1.y);
        const __half2* s0 = (const __half2*)(g_xh + (size_t)e0.x * XP);
        const __half2* s1 = (const __half2*)(g_xh + (size_t)e1.x * XP);
        float2 f0 = __half22float2(s0[lane]);
        float2 f1 = __half22float2(s1[lane]);
        a0.x = fmaf(v0, f0.x, a0.x); a0.y = fmaf(v0, f0.y, a0.y);
        b0.x = fmaf(v1, f1.x, b0.x); b0.y = fmaf(v1, f1.y, b0.y);
        if (lane < 16) {
            float2 g0 = __half22float2(s0[32 + lane]);
            float2 g1 = __half22float2(s1[32 + lane]);
            a1.x = fmaf(v0, g0.x, a1.x); a1.y = fmaf(v0, g0.y, a1.y);
            b1.x = fmaf(v1, g1.x, b1.x); b1.y = fmaf(v1, g1.y, b1.y);
        }
    }
    if (j < e) {
        int2 e0 = g_edge[j];
        float v0 = __int_as_float(e0.y);
        const __half2* s0 = (const __half2*)(g_xh + (size_t)e0.x * XP);
        float2 f0 = __half22float2(s0[lane]);
        a0.x = fmaf(v0, f0.x, a0.x); a0.y = fmaf(v0, f0.y, a0.y);
        if (lane < 16) {
            float2 g0 = __half22float2(s0[32 + lane]);
            a1.x = fmaf(v0, g0.x, a1.x); a1.y = fmaf(v0, g0.y, a1.y);
        }
    }
    __half2* dst = (__half2*)(g_axh + (size_t)w * XP);
    dst[lane] = __floats2half2_rn(a0.x + b0.x, a0.y + b0.y);
    if (lane < 16)
        dst[32 + lane] = __floats2half2_rn(a1.x + b1.x, a1.y + b1.y);
}

// ---------------- 4+5 fused fp16 ldmatrix: z = relu(ax@W1+b1)@W2 -----------
#define AST  104
#define B1ST 136
#define HST  136
#define W2ST 40
#define OFF_AS  0
#define OFF_B1  (128 * AST * 2)
#define OFF_HS  (OFF_B1 + 96 * B1ST * 2)
#define OFF_W2  (OFF_HS + 128 * HST * 2)
#define OFF_SB1 (OFF_W2 + 128 * W2ST * 2)
#define FUSED_SMEM (OFF_SB1 + D_HID * 4)

__device__ __forceinline__ void ldsm_x4(uint32_t* r, uint32_t addr) {
    asm volatile("ldmatrix.sync.aligned.m8n8.x4.shared.b16 {%0,%1,%2,%3}, [%4];"
        : "=r"(r[0]), "=r"(r[1]), "=r"(r[2]), "=r"(r[3]) : "r"(addr));
}
__device__ __forceinline__ void ldsm_x4_t(uint32_t* r, uint32_t addr) {
    asm volatile("ldmatrix.sync.aligned.m8n8.x4.trans.shared.b16 {%0,%1,%2,%3}, [%4];"
        : "=r"(r[0]), "=r"(r[1]), "=r"(r[2]), "=r"(r[3]) : "r"(addr));
}
__device__ __forceinline__ void mma_f16(float* d, const uint32_t* a, const uint32_t* b) {
    asm volatile(
        "mma.sync.aligned.m16n8k16.row.col.f32.f16.f16.f32 "
        "{%0,%1,%2,%3}, {%4,%5,%6,%7}, {%8,%9}, {%0,%1,%2,%3};"
        : "+f"(d[0]), "+f"(d[1]), "+f"(d[2]), "+f"(d[3])
        : "r"(a[0]), "r"(a[1]), "r"(a[2]), "r"(a[3]), "r"(b[0]), "r"(b[1]));
}

__global__ __launch_bounds__(256, 2) void fused_gemm_kernel(const float* __restrict__ b1) {
    extern __shared__ __align__(16) char smem_raw[];
    __half* As  = (__half*)(smem_raw + OFF_AS);
    __half* B1s = (__half*)(smem_raw + OFF_B1);
    __half* Hs  = (__half*)(smem_raw + OFF_HS);
    __half* W2s = (__half*)(smem_raw + OFF_W2);
    float*  sB1 = (float*)(smem_raw + OFF_SB1);
    uint32_t sbase = smem_u32(smem_raw);

    int t = threadIdx.x;
    int wid = t >> 5, lane = t & 31;
    int g = lane >> 2, tg = lane & 3;
    int l15 = lane & 15;
    int off8 = (lane >> 4) << 3;
    int m0 = blockIdx.x * 128;

    #pragma unroll
    for (int it = 0; it < 6; it++) {
        int flat = it * 256 + t;
        int rr = flat / 12, q = flat % 12;
        uint4 v = make_uint4(0u, 0u, 0u, 0u);
        int gr = m0 + rr;
        if (gr < N_NODES) v = *(const uint4*)&g_axh[(size_t)gr * XP + q * 8];
        *(uint4*)(As + rr * AST + q * 8) = v;
    }
    for (int i = t; i < D_HID; i += 256) sB1[i] = b1[i];

    int wm = (wid & 1) * 64;
    int wn = (wid >> 1) * 32;

    float accz[4][4];
    #pragma unroll
    for (int ct = 0; ct < 4; ct++)
        #pragma unroll
        for (int i = 0; i < 4; i++) accz[ct][i] = 0.f;

    for (int nt = 0; nt < 8; nt++) {
        int n0 = nt * 128;
        // stage W1 n-tile: pure uint4 copies from preconverted g_w1h
        #pragma unroll
        for (int it = 0; it < 6; it++) {
            int flat = it * 256 + t;          // 96 rows x 16 uint4
            int k = flat >> 4, q = flat & 15;
            uint4 v = *(const uint4*)&g_w1h[k * D_HID + n0 + q * 8];
            *(uint4*)(B1s + k * B1ST + q * 8) = v;
        }
        // stage W2 k-slice: 128 rows x 4 uint4
        #pragma unroll
        for (int it = 0; it < 2; it++) {
            int flat = it * 256 + t;
            int kk = flat >> 2, q = flat & 3;
            uint4 v = *(const uint4*)&g_w2h[(n0 + kk) * 32 + q * 8];
            *(uint4*)(W2s + kk * W2ST + q * 8) = v;
        }
        __syncthreads();

        #pragma unroll
        for (int n2h = 0; n2h < 2; n2h++) {
            float acc1[4][2][4];
            #pragma unroll
            for (int mt = 0; mt < 4; mt++)
                #pragma unroll
                for (int n2 = 0; n2 < 2; n2++)
                    #pragma unroll
                    for (int i = 0; i < 4; i++) acc1[mt][n2][i] = 0.f;

            #pragma unroll
            for (int ks = 0; ks < 6; ks++) {
                int k0 = ks * 16;
                uint32_t a[4][4];
                #pragma unroll
                for (int mt = 0; mt < 4; mt++)
                    ldsm_x4(a[mt], sbase + OFF_AS +
                            ((wm + mt * 16 + l15) * AST + k0 + off8) * 2);
                uint32_t bf[4];
                ldsm_x4_t(bf, sbase + OFF_B1 +
                          ((k0 + l15) * B1ST + wn + n2h * 16 + off8) * 2);
                #pragma unroll
                for (int mt = 0; mt < 4; mt++) {
                    mma_f16(acc1[mt][0], a[mt], bf + 0);
                    mma_f16(acc1[mt][1], a[mt], bf + 2);
                }
            }
            #pragma unroll
            for (int n2 = 0; n2 < 2; n2++) {
                int col = wn + n2h * 16 + n2 * 8 + tg * 2;
                float bz0 = sB1[n0 + col], bz1 = sB1[n0 + col + 1];
                #pragma unroll
                for (int mt = 0; mt < 4; mt++) {
                    int r0 = wm + mt * 16 + g;
                    *(__half2*)(Hs + r0 * HST + col) =
                        __floats2half2_rn(fmaxf(acc1[mt][n2][0] + bz0, 0.f),
                                          fmaxf(acc1[mt][n2][1] + bz1, 0.f));
                    *(__half2*)(Hs + (r0 + 8) * HST + col) =
                        __floats2half2_rn(fmaxf(acc1[mt][n2][2] + bz0, 0.f),
                                          fmaxf(acc1[mt][n2][3] + bz1, 0.f));
                }
            }
        }
        __syncthreads();

        #pragma unroll
        for (int ks = 0; ks < 8; ks++) {
            int k0 = ks * 16;
            uint32_t ah[4];
            ldsm_x4(ah, sbase + OFF_HS + ((wid * 16 + l15) * HST + k0 + off8) * 2);
            uint32_t bw[8];
            ldsm_x4_t(bw + 0, sbase + OFF_W2 + ((k0 + l15) * W2ST + 0 + off8) * 2);
            ldsm_x4_t(bw + 4, sbase + OFF_W2 + ((k0 + l15) * W2ST + 16 + off8) * 2);
            mma_f16(accz[0], ah, bw + 0);
            mma_f16(accz[1], ah, bw + 2);
            mma_f16(accz[2], ah, bw + 4);
            mma_f16(accz[3], ah, bw + 6);
        }
        __syncthreads();
    }

    #pragma unroll
    for (int ct = 0; ct < 4; ct++) {
        int col = ct * 8 + tg * 2;
        int r0 = m0 + wid * 16 + g;
        if (r0 < N_NODES)
            *(__half2*)&g_zh[(size_t)r0 * ZP + col] =
                __floats2half2_rn(accz[ct][0], accz[ct][1]);
        int r1 = r0 + 8;
        if (r1 < N_NODES)
            *(__half2*)&g_zh[(size_t)r1 * ZP + col] =
                __floats2half2_rn(accz[ct][2], accz[ct][3]);
    }
}

// ---------------- 7. SpMM2: dual-half warp, same row, shfl combine ---------
__global__ void spmm_z_csr_kernel(const float* __restrict__ b2,
                                  float* __restrict__ out) {
    int w = (blockIdx.x * blockDim.x + threadIdx.x) >> 5;
    int lane = threadIdx.x & 31;
    if (w >= N_NODES) return;
    int s = g_rowptr[w], e = g_rowptr[w + 1];
    int hi = lane >> 4;
    int c = lane & 15;
    bool act = c < 13;
    float2 acc = make_float2(0.f, 0.f);
    int j = s;
    for (; j + 1 < e; j += 2) {
        int2 ee = g_edge[j + hi];
        float v = __int_as_float(ee.y);
        if (act) {
            float2 f = __half22float2(((const __half2*)(g_zh + (size_t)ee.x * ZP))[c]);
            acc.x = fmaf(v, f.x, acc.x);
            acc.y = fmaf(v, f.y, acc.y);
        }
    }
    if (j < e && hi == 0) {
        int2 ee = g_edge[j];
        float v = __int_as_float(ee.y);
        if (act) {
            float2 f = __half22float2(((const __half2*)(g_zh + (size_t)ee.x * ZP))[c]);
            acc.x = fmaf(v, f.x, acc.x);
            acc.y = fmaf(v, f.y, acc.y);
        }
    }
    acc.x += __shfl_down_sync(0xffffffffu, acc.x, 16);
    acc.y += __shfl_down_sync(0xffffffffu, acc.y, 16);
    if (lane < 13) {
        int c0 = lane * 2;
        out[(size_t)w * NC + c0] = acc.x + b2[c0];
        if (c0 + 1 < NC)
            out[(size_t)w * NC + c0 + 1] = acc.y + b2[c0 + 1];
    }
}

// ---------------- launch ----------------
extern "C" void kernel_launch(void* const* d_in, const int* in_sizes, int n_in,
                              void* d_out, int out_size) {
    const float* feature = (const float*)d_in[0];
    const float* conv_w  = (const float*)d_in[1];
    const float* conv_b  = (const float*)d_in[2];
    const float* W1      = (const float*)d_in[3];
    const float* b1      = (const float*)d_in[4];
    const float* W2      = (const float*)d_in[5];
    const float* b2      = (const float*)d_in[6];
    const float* adj_val = (const float*)d_in[7];
    const int*   e_row   = (const int*)d_in[8];
    const int*   e_col   = (const int*)d_in[9];
    float* out = (float*)d_out;

    cudaFuncSetAttribute(fused_gemm_kernel, cudaFuncAttributeMaxDynamicSharedMemorySize, FUSED_SMEM);

    const int EB = (N_EDGES + 255) / 256;
    const int WB = (N_NODES * 32 + 255) / 256;

    prep_w_kernel<<<256, 256>>>(W1, W2);
    {
        dim3 blk(96, CONV_Y);
        conv_relu_kernel<<<N_NODES / CONV_Y, blk>>>(feature, conv_w, conv_b);
    }
    count_kernel<<<EB, 256>>>(e_row);
    scan1_kernel<<<NBLK2, 512>>>();
    scan23_kernel<<<NBLK2, 512>>>();
    scatter_kernel<<<EB, 256>>>(adj_val, e_row, e_col);
    spmm_x_csr_kernel<<<WB, 256>>>();
    fused_gemm_kernel<<<(N_NODES + 127) / 128, 256, FUSED_SMEM>>>(b1);
    spmm_z_csr_kernel<<<WB, 256>>>(b2, out);
}

// round 17
// speedup vs baseline: 1.1447x; 1.0050x over previous
#include <cuda_runtime.h>
#include <cuda_fp16.h>
#include <cstdint>

#define N_NODES 100000
#define N_EDGES 3200000
#define D_IN 83
#define XP 96          // x/ax row stride in halves (192B)
#define D_HID 1024
#define NC 25
#define ZP 32          // z row stride in halves (64B)
#define NBLK2 196      // ceil(N_NODES/512)
#define CONV_Y 4       // nodes per conv block

#define CONV_BLKS  (N_NODES / CONV_Y)          // 25000
#define COUNT_BLKS ((N_EDGES + 383) / 384)     // 8334
#define PREP_ITEMS (96 * 512 + D_HID * 16)     // 65536 half2 items
#define PREP_BLKS  ((PREP_ITEMS + 383) / 384)  // 171
#define FRONT_BLKS (CONV_BLKS + COUNT_BLKS + PREP_BLKS)

// ---------------- scratch ----------------
__device__ __half g_xh[(size_t)N_NODES * XP];
__device__ __half g_axh[(size_t)N_NODES * XP];
__device__ __half g_zh[(size_t)N_NODES * ZP];
__device__ __half g_w1h[96 * D_HID];      // W1 fp16, k-padded to 96
__device__ __half g_w2h[D_HID * 32];      // W2 fp16, c-padded to 32
__device__ int    g_cnt[N_NODES];         // zero-init at load; scan1 re-zeroes
__device__ int    g_rowptr[N_NODES + 1];
__device__ int    g_cur[N_NODES + 1];
__device__ int    g_bsum[NBLK2];
__device__ int2   g_edge[N_EDGES];

__device__ __forceinline__ uint32_t smem_u32(const void* p) {
    uint32_t a;
    asm("{ .reg .u64 t; cvta.to.shared.u64 t, %1; cvt.u32.u64 %0, t; }" : "=r"(a) : "l"(p));
    return a;
}

// ---------------- 1. merged front: conv | count | prep_w -------------------
__global__ __launch_bounds__(384) void front_kernel(const float* __restrict__ feat,
                                                    const float* __restrict__ conv_w,
                                                    const float* __restrict__ conv_b,
                                                    const float* __restrict__ W1,
                                                    const float* __restrict__ W2,
                                                    const int* __restrict__ e_row) {
    int b = blockIdx.x;
    int t = threadIdx.x;
    if (b < CONV_BLKS) {
        // ---- conv: 4 nodes/block ----
        __shared__ float srow[CONV_Y][D_IN];
        __shared__ float sw[5];
        __shared__ float sb;
        int tx = t % 96, ty = t / 96;
        int n = b * CONV_Y + ty;
        if (ty == 0) {
            if (tx < 5) sw[tx] = conv_w[tx] + conv_w[5 + tx] + conv_w[10 + tx] + conv_w[15 + tx];
            if (tx == 5) sb = conv_b[0] + conv_b[1] + conv_b[2] + conv_b[3];
        }
        if (tx < D_IN) srow[ty][tx] = feat[(size_t)n * D_IN + tx];
        __syncthreads();
        float r = 0.f;
        if (tx < D_IN) {
            float s = sb;
            #pragma unroll
            for (int k = 0; k < 5; k++) {
                int j = tx + k - 2;
                if (j >= 0 && j < D_IN) s += srow[ty][j] * sw[k];
            }
            r = fmaxf(s, 0.f);
        }
        g_xh[(size_t)n * XP + tx] = __float2half_rn(r);
    } else if (b < CONV_BLKS + COUNT_BLKS) {
        // ---- count ----
        int e = (b - CONV_BLKS) * 384 + t;
        if (e < N_EDGES) atomicAdd(&g_cnt[e_row[e]], 1);
    } else {
        // ---- prep weights ----
        int i = (b - CONV_BLKS - COUNT_BLKS) * 384 + t;
        if (i < 96 * 512) {                       // W1h half2s
            int k = i >> 9, n2 = i & 511;
            float2 v = make_float2(0.f, 0.f);
            if (k < D_IN) v = *(const float2*)&W1[(size_t)k * D_HID + n2 * 2];
            ((__half2*)g_w1h)[i] = __floats2half2_rn(v.x, v.y);
        } else if (i < PREP_ITEMS) {              // W2h half2s
            int j = i - 96 * 512;
            int kk = j >> 4, c = (j & 15) * 2;
            float w0 = (c < NC) ? W2[(size_t)kk * NC + c] : 0.f;
            float w1 = (c + 1 < NC) ? W2[(size_t)kk * NC + c + 1] : 0.f;
            ((__half2*)g_w2h)[j] = __floats2half2_rn(w0, w1);
        }
    }
}

// ---------------- CSR scans ----------------
__global__ void scan1_kernel() {
    __shared__ int s[512];
    int t = threadIdx.x;
    int i = blockIdx.x * 512 + t;
    int v = (i < N_NODES) ? g_cnt[i] : 0;
    if (i < N_NODES) g_cnt[i] = 0;          // reset for next graph replay
    s[t] = v;
    __syncthreads();
    #pragma unroll
    for (int d = 1; d < 512; d <<= 1) {
        int x = (t >= d) ? s[t - d] : 0;
        __syncthreads();
        s[t] += x;
        __syncthreads();
    }
    if (i < N_NODES) g_rowptr[i + 1] = s[t];
    if (t == 511) g_bsum[blockIdx.x] = s[511];
}
// scan2+scan3 merged
__global__ void scan23_kernel() {
    __shared__ int sb[512];
    int t = threadIdx.x;
    sb[t] = (t < NBLK2) ? g_bsum[t] : 0;
    __syncthreads();
    #pragma unroll
    for (int d = 1; d < 512; d <<= 1) {
        int x = (t >= d) ? sb[t - d] : 0;
        __syncthreads();
        sb[t] += x;
        __syncthreads();
    }
    int b = blockIdx.x;
    int offv = (b > 0) ? sb[b - 1] : 0;
    int i = b * 512 + t;
    if (i < N_NODES) {
        int val = g_rowptr[i + 1] + offv;
        g_rowptr[i + 1] = val;
        g_cur[i + 1] = val;
    }
    if (i == 0) { g_rowptr[0] = 0; g_cur[0] = 0; }
}
__global__ void scatter_kernel(const float* __restrict__ val,
                               const int* __restrict__ row,
                               const int* __restrict__ col) {
    int e = blockIdx.x * blockDim.x + threadIdx.x;
    if (e < N_EDGES) {
        int r = row[e];
        int pos = atomicAdd(&g_cur[r], 1);
        g_edge[pos] = make_int2(col[e], __float_as_int(val[e]));
    }
}

// ---------------- 3. SpMM1 (gather, proven 2-edge unroll) ------------------
__global__ void spmm_x_csr_kernel() {
    int w = (blockIdx.x * blockDim.x + threadIdx.x) >> 5;
    int lane = threadIdx.x & 31;
    if (w >= N_NODES) return;
    int s = g_rowptr[w], e = g_rowptr[w + 1];
    float2 a0 = make_float2(0.f, 0.f), a1 = make_float2(0.f, 0.f);
    float2 b0 = make_float2(0.f, 0.f), b1 = make_float2(0.f, 0.f);
    int j = s;
    for (; j + 1 < e; j += 2) {
        int2 e0 = g_edge[j], e1 = g_edge[j + 1];
        float v0 = __int_as_float(e0.y), v1 = __int_as_float(e1.y);
        const __half2* s0 = (const __half2*)(g_xh + (size_t)e0.x * XP);
        const __half2* s1 = (const __half2*)(g_xh + (size_t)e1.x * XP);
        float2 f0 = __half22float2(s0[lane]);
        float2 f1 = __half22float2(s1[lane]);
        a0.x = fmaf(v0, f0.x, a0.x); a0.y = fmaf(v0, f0.y, a0.y);
        b0.x = fmaf(v1, f1.x, b0.x); b0.y = fmaf(v1, f1.y, b0.y);
        if (lane < 16) {
            float2 g0 = __half22float2(s0[32 + lane]);
            float2 g1 = __half22float2(s1[32 + lane]);
            a1.x = fmaf(v0, g0.x, a1.x); a1.y = fmaf(v0, g0.y, a1.y);
            b1.x = fmaf(v1, g1.x, b1.x); b1.y = fmaf(v1, g1.y, b1.y);
        }
    }
    if (j < e) {
        int2 e0 = g_edge[j];
        float v0 = __int_as_float(e0.y);
        const __half2* s0 = (const __half2*)(g_xh + (size_t)e0.x * XP);
        float2 f0 = __half22float2(s0[lane]);
        a0.x = fmaf(v0, f0.x, a0.x); a0.y = fmaf(v0, f0.y, a0.y);
        if (lane < 16) {
            float2 g0 = __half22float2(s0[32 + lane]);
            a1.x = fmaf(v0, g0.x, a1.x); a1.y = fmaf(v0, g0.y, a1.y);
        }
    }
    __half2* dst = (__half2*)(g_axh + (size_t)w * XP);
    dst[lane] = __floats2half2_rn(a0.x + b0.x, a0.y + b0.y);
    if (lane < 16)
        dst[32 + lane] = __floats2half2_rn(a1.x + b1.x, a1.y + b1.y);
}

// ---------------- 4+5 fused fp16 ldmatrix: z = relu(ax@W1+b1)@W2 -----------
#define AST  104
#define B1ST 136
#define HST  136
#define W2ST 40
#define OFF_AS  0
#define OFF_B1  (128 * AST * 2)
#define OFF_HS  (OFF_B1 + 96 * B1ST * 2)
#define OFF_W2  (OFF_HS + 128 * HST * 2)
#define OFF_SB1 (OFF_W2 + 128 * W2ST * 2)
#define FUSED_SMEM (OFF_SB1 + D_HID * 4)

__device__ __forceinline__ void ldsm_x4(uint32_t* r, uint32_t addr) {
    asm volatile("ldmatrix.sync.aligned.m8n8.x4.shared.b16 {%0,%1,%2,%3}, [%4];"
        : "=r"(r[0]), "=r"(r[1]), "=r"(r[2]), "=r"(r[3]) : "r"(addr));
}
__device__ __forceinline__ void ldsm_x4_t(uint32_t* r, uint32_t addr) {
    asm volatile("ldmatrix.sync.aligned.m8n8.x4.trans.shared.b16 {%0,%1,%2,%3}, [%4];"
        : "=r"(r[0]), "=r"(r[1]), "=r"(r[2]), "=r"(r[3]) : "r"(addr));
}
__device__ __forceinline__ void mma_f16(float* d, const uint32_t* a, const uint32_t* b) {
    asm volatile(
        "mma.sync.aligned.m16n8k16.row.col.f32.f16.f16.f32 "
        "{%0,%1,%2,%3}, {%4,%5,%6,%7}, {%8,%9}, {%0,%1,%2,%3};"
        : "+f"(d[0]), "+f"(d[1]), "+f"(d[2]), "+f"(d[3])
        : "r"(a[0]), "r"(a[1]), "r"(a[2]), "r"(a[3]), "r"(b[0]), "r"(b[1]));
}

__global__ __launch_bounds__(256, 2) void fused_gemm_kernel(const float* __restrict__ b1) {
    extern __shared__ __align__(16) char smem_raw[];
    __half* As  = (__half*)(smem_raw + OFF_AS);
    __half* B1s = (__half*)(smem_raw + OFF_B1);
    __half* Hs  = (__half*)(smem_raw + OFF_HS);
    __half* W2s = (__half*)(smem_raw + OFF_W2);
    float*  sB1 = (float*)(smem_raw + OFF_SB1);
    uint32_t sbase = smem_u32(smem_raw);

    int t = threadIdx.x;
    int wid = t >> 5, lane = t & 31;
    int g = lane >> 2, tg = lane & 3;
    int l15 = lane & 15;
    int off8 = (lane >> 4) << 3;
    int m0 = blockIdx.x * 128;

    #pragma unroll
    for (int it = 0; it < 6; it++) {
        int flat = it * 256 + t;
        int rr = flat / 12, q = flat % 12;
        uint4 v = make_uint4(0u, 0u, 0u, 0u);
        int gr = m0 + rr;
        if (gr < N_NODES) v = *(const uint4*)&g_axh[(size_t)gr * XP + q * 8];
        *(uint4*)(As + rr * AST + q * 8) = v;
    }
    for (int i = t; i < D_HID; i += 256) sB1[i] = b1[i];

    int wm = (wid & 1) * 64;
    int wn = (wid >> 1) * 32;

    float accz[4][4];
    #pragma unroll
    for (int ct = 0; ct < 4; ct++)
        #pragma unroll
        for (int i = 0; i < 4; i++) accz[ct][i] = 0.f;

    for (int nt = 0; nt < 8; nt++) {
        int n0 = nt * 128;
        #pragma unroll
        for (int it = 0; it < 6; it++) {
            int flat = it * 256 + t;          // 96 rows x 16 uint4
            int k = flat >> 4, q = flat & 15;
            uint4 v = *(const uint4*)&g_w1h[k * D_HID + n0 + q * 8];
            *(uint4*)(B1s + k * B1ST + q * 8) = v;
        }
        #pragma unroll
        for (int it = 0; it < 2; it++) {
            int flat = it * 256 + t;
            int kk = flat >> 2, q = flat & 3;
            uint4 v = *(const uint4*)&g_w2h[(n0 + kk) * 32 + q * 8];
            *(uint4*)(W2s + kk * W2ST + q * 8) = v;
        }
        __syncthreads();

        #pragma unroll
        for (int n2h = 0; n2h < 2; n2h++) {
            float acc1[4][2][4];
            #pragma unroll
            for (int mt = 0; mt < 4; mt++)
                #pragma unroll
                for (int n2 = 0; n2 < 2; n2++)
                    #pragma unroll
                    for (int i = 0; i < 4; i++) acc1[mt][n2][i] = 0.f;

            #pragma unroll
            for (int ks = 0; ks < 6; ks++) {
                int k0 = ks * 16;
                uint32_t a[4][4];
                #pragma unroll
                for (int mt = 0; mt < 4; mt++)
                    ldsm_x4(a[mt], sbase + OFF_AS +
                            ((wm + mt * 16 + l15) * AST + k0 + off8) * 2);
                uint32_t bf[4];
                ldsm_x4_t(bf, sbase + OFF_B1 +
                          ((k0 + l15) * B1ST + wn + n2h * 16 + off8) * 2);
                #pragma unroll
                for (int mt = 0; mt < 4; mt++) {
                    mma_f16(acc1[mt][0], a[mt], bf + 0);
                    mma_f16(acc1[mt][1], a[mt], bf + 2);
                }
            }
            #pragma unroll
            for (int n2 = 0; n2 < 2; n2++) {
                int col = wn + n2h * 16 + n2 * 8 + tg * 2;
                float bz0 = sB1[n0 + col], bz1 = sB1[n0 + col + 1];
                #pragma unroll
                for (int mt = 0; mt < 4; mt++) {
                    int r0 = wm + mt * 16 + g;
                    *(__half2*)(Hs + r0 * HST + col) =
                        __floats2half2_rn(fmaxf(acc1[mt][n2][0] + bz0, 0.f),
                                          fmaxf(acc1[mt][n2][1] + bz1, 0.f));
                    *(__half2*)(Hs + (r0 + 8) * HST + col) =
                        __floats2half2_rn(fmaxf(acc1[mt][n2][2] + bz0, 0.f),
                                          fmaxf(acc1[mt][n2][3] + bz1, 0.f));
                }
            }
        }
        __syncthreads();

        #pragma unroll
        for (int ks = 0; ks < 8; ks++) {
            int k0 = ks * 16;
            uint32_t ah[4];
            ldsm_x4(ah, sbase + OFF_HS + ((wid * 16 + l15) * HST + k0 + off8) * 2);
            uint32_t bw[8];
            ldsm_x4_t(bw + 0, sbase + OFF_W2 + ((k0 + l15) * W2ST + 0 + off8) * 2);
            ldsm_x4_t(bw + 4, sbase + OFF_W2 + ((k0 + l15) * W2ST + 16 + off8) * 2);
            mma_f16(accz[0], ah, bw + 0);
            mma_f16(accz[1], ah, bw + 2);
            mma_f16(accz[2], ah, bw + 4);
            mma_f16(accz[3], ah, bw + 6);
        }
        __syncthreads();
    }

    #pragma unroll
    for (int ct = 0; ct < 4; ct++) {
        int col = ct * 8 + tg * 2;
        int r0 = m0 + wid * 16 + g;
        if (r0 < N_NODES)
            *(__half2*)&g_zh[(size_t)r0 * ZP + col] =
                __floats2half2_rn(accz[ct][0], accz[ct][1]);
        int r1 = r0 + 8;
        if (r1 < N_NODES)
            *(__half2*)&g_zh[(size_t)r1 * ZP + col] =
                __floats2half2_rn(accz[ct][2], accz[ct][3]);
    }
}

// ---------------- 7. SpMM2: dual-half warp, same row, shfl combine ---------
__global__ void spmm_z_csr_kernel(const float* __restrict__ b2,
                                  float* __restrict__ out) {
    int w = (blockIdx.x * blockDim.x + threadIdx.x) >> 5;
    int lane = threadIdx.x & 31;
    if (w >= N_NODES) return;
    int s = g_rowptr[w], e = g_rowptr[w + 1];
    int hi = lane >> 4;
    int c = lane & 15;
    bool act = c < 13;
    float2 acc = make_float2(0.f, 0.f);
    int j = s;
    for (; j + 1 < e; j += 2) {
        int2 ee = g_edge[j + hi];
        float v = __int_as_float(ee.y);
        if (act) {
            float2 f = __half22float2(((const __half2*)(g_zh + (size_t)ee.x * ZP))[c]);
            acc.x = fmaf(v, f.x, acc.x);
            acc.y = fmaf(v, f.y, acc.y);
        }
    }
    if (j < e && hi == 0) {
        int2 ee = g_edge[j];
        float v = __int_as_float(ee.y);
        if (act) {
            float2 f = __half22float2(((const __half2*)(g_zh + (size_t)ee.x * ZP))[c]);
            acc.x = fmaf(v, f.x, acc.x);
            acc.y = fmaf(v, f.y, acc.y);
        }
    }
    acc.x += __shfl_down_sync(0xffffffffu, acc.x, 16);
    acc.y += __shfl_down_sync(0xffffffffu, acc.y, 16);
    if (lane < 13) {
        int c0 = lane * 2;
        out[(size_t)w * NC + c0] = acc.x + b2[c0];
        if (c0 + 1 < NC)
            out[(size_t)w * NC + c0 + 1] = acc.y + b2[c0 + 1];
    }
}

// ---------------- launch ----------------
extern "C" void kernel_launch(void* const* d_in, const int* in_sizes, int n_in,
                              void* d_out, int out_size) {
    const float* feature = (const float*)d_in[0];
    const float* conv_w  = (const float*)d_in[1];
    const float* conv_b  = (const float*)d_in[2];
    const float* W1      = (const float*)d_in[3];
    const float* b1      = (const float*)d_in[4];
    const float* W2      = (const float*)d_in[5];
    const float* b2      = (const float*)d_in[6];
    const float* adj_val = (const float*)d_in[7];
    const int*   e_row   = (const int*)d_in[8];
    const int*   e_col   = (const int*)d_in[9];
    float* out = (float*)d_out;

    cudaFuncSetAttribute(fused_gemm_kernel, cudaFuncAttributeMaxDynamicSharedMemorySize, FUSED_SMEM);

    const int EB = (N_EDGES + 255) / 256;
    const int WB = (N_NODES * 32 + 255) / 256;

    front_kernel<<<FRONT_BLKS, 384>>>(feature, conv_w, conv_b, W1, W2, e_row);
    scan1_kernel<<<NBLK2, 512>>>();
    scan23_kernel<<<NBLK2, 512>>>();
    scatter_kernel<<<EB, 256>>>(adj_val, e_row, e_col);
    spmm_x_csr_kernel<<<WB, 256>>>();
    fused_gemm_kernel<<<(N_NODES + 127) / 128, 256, FUSED_SMEM>>>(b1);
    spmm_z_csr_kernel<<<WB, 256>>>(b2, out);
}